// round 3
// baseline (speedup 1.0000x reference)
#include <cuda_runtime.h>

#define Bb   2
#define Tt   1024
#define Cc   1024
#define Hh   16
#define Dd   64
#define Pp   3
#define Ee   8
#define DFF  1024
#define NN   (Bb*Tt)          // 2048 tokens
#define C3   (3*Cc)           // 3072

// ---------------- scratch (static device allocations) ----------------
__device__ float g_qkv[NN*C3];                 // (B,T,3,H,D) flattened
__device__ float g_cat[NN*C3];                 // concat of 3 phase outputs
__device__ float g_scores[Bb*Hh*Tt*Tt];        // raw attention logits
__device__ float g_attn[Bb*Hh*Tt*Tt];          // post-softmax(+prior) attn
__device__ float g_y[NN*Cc];                   // merged + residual
__device__ float g_xn[NN*Cc];                  // layernorm output
__device__ float g_mean[Bb*Cc];                // mean-pooled tokens
__device__ float g_scale[Bb*Hh];               // ds * awareness
__device__ int   g_cursor[Ee];
__device__ int   g_tok[Ee*NN];
__device__ float g_wgt[Ee*NN];
__device__ float g_act[Ee*NN*DFF];             // expert hidden activations

// ---------------- block reductions ----------------
__device__ __forceinline__ float blockReduceSum(float v) {
    __shared__ float sh[8];
    int lane = threadIdx.x & 31, w = threadIdx.x >> 5;
    #pragma unroll
    for (int o = 16; o; o >>= 1) v += __shfl_xor_sync(0xffffffffu, v, o);
    if (lane == 0) sh[w] = v;
    __syncthreads();
    float r = 0.f;
    #pragma unroll
    for (int i = 0; i < 8; i++) r += sh[i];
    __syncthreads();
    return r;
}
__device__ __forceinline__ float blockReduceMax(float v) {
    __shared__ float sh[8];
    int lane = threadIdx.x & 31, w = threadIdx.x >> 5;
    #pragma unroll
    for (int o = 16; o; o >>= 1) v = fmaxf(v, __shfl_xor_sync(0xffffffffu, v, o));
    if (lane == 0) sh[w] = v;
    __syncthreads();
    float r = -1e30f;
    #pragma unroll
    for (int i = 0; i < 8; i++) r = fmaxf(r, sh[i]);
    __syncthreads();
    return r;
}

// ---------------- generic C = A @ B^T gemm, 128x128x16 tiles ----------------
// batched via z: off = (z/zdiv)*s1 + (z%zdiv)*s2 for A, B, C independently.
// epilogue: *scale_z[z], +bias[n], +addsrc[m,n], optional silu.
__global__ __launch_bounds__(256) void k_gemm_abT(
    const float* __restrict__ A, int lda, long long sA1, long long sA2,
    const float* __restrict__ B, int ldb, long long sB1, long long sB2,
    const float* __restrict__ bias,
    float* __restrict__ C, int ldc, long long sC1, long long sC2,
    int K, int zdiv,
    const float* __restrict__ scale_z,
    const float* __restrict__ addsrc, int ldadd,
    int act)
{
    __shared__ float As[16][132];
    __shared__ float Bs[16][132];
    int z = blockIdx.z, z1 = z / zdiv, z2 = z % zdiv;
    A += z1 * sA1 + z2 * sA2;
    B += z1 * sB1 + z2 * sB2;
    C += z1 * sC1 + z2 * sC2;
    const int m0 = blockIdx.x * 128, n0 = blockIdx.y * 128;
    const int tid = threadIdx.x;
    const int tr = tid >> 4, tc = tid & 15;
    float acc[8][8];
    #pragma unroll
    for (int i = 0; i < 8; i++)
        #pragma unroll
        for (int j = 0; j < 8; j++) acc[i][j] = 0.f;

    for (int k0 = 0; k0 < K; k0 += 16) {
        #pragma unroll
        for (int rep = 0; rep < 2; rep++) {
            int v = rep * 256 + tid;
            int r = v >> 2, c4 = (v & 3) * 4;
            float4 ta = *reinterpret_cast<const float4*>(&A[(long long)(m0 + r) * lda + k0 + c4]);
            As[c4 + 0][r] = ta.x; As[c4 + 1][r] = ta.y; As[c4 + 2][r] = ta.z; As[c4 + 3][r] = ta.w;
            float4 tb = *reinterpret_cast<const float4*>(&B[(long long)(n0 + r) * ldb + k0 + c4]);
            Bs[c4 + 0][r] = tb.x; Bs[c4 + 1][r] = tb.y; Bs[c4 + 2][r] = tb.z; Bs[c4 + 3][r] = tb.w;
        }
        __syncthreads();
        #pragma unroll
        for (int kk = 0; kk < 16; kk++) {
            float a[8], b[8];
            *reinterpret_cast<float4*>(a)     = *reinterpret_cast<const float4*>(&As[kk][tr * 8]);
            *reinterpret_cast<float4*>(a + 4) = *reinterpret_cast<const float4*>(&As[kk][tr * 8 + 4]);
            *reinterpret_cast<float4*>(b)     = *reinterpret_cast<const float4*>(&Bs[kk][tc * 8]);
            *reinterpret_cast<float4*>(b + 4) = *reinterpret_cast<const float4*>(&Bs[kk][tc * 8 + 4]);
            #pragma unroll
            for (int i = 0; i < 8; i++)
                #pragma unroll
                for (int j = 0; j < 8; j++) acc[i][j] = fmaf(a[i], b[j], acc[i][j]);
        }
        __syncthreads();
    }
    float sc = scale_z ? scale_z[z] : 1.f;
    #pragma unroll
    for (int i = 0; i < 8; i++) {
        int m = m0 + tr * 8 + i;
        #pragma unroll
        for (int jj = 0; jj < 2; jj++) {
            int n = n0 + tc * 8 + jj * 4;
            float4 o;
            float* op = &o.x;
            #pragma unroll
            for (int j = 0; j < 4; j++) {
                float v = acc[i][jj * 4 + j] * sc;
                int nn = n + j;
                if (bias)   v += bias[nn];
                if (addsrc) v += addsrc[(long long)m * ldadd + nn];
                if (act)    v = v / (1.f + __expf(-v));
                op[j] = v;
            }
            *reinterpret_cast<float4*>(&C[(long long)m * ldc + n]) = o;
        }
    }
}

// ---------------- C = A @ B (row-major B), N=64, with silu epilogue (AV) ----
__global__ __launch_bounds__(256) void k_gemm_ab_silu(
    const float* __restrict__ A, int lda, long long sA1, long long sA2,
    const float* __restrict__ B, int ldb, long long sB1, long long sB2,
    float* __restrict__ C, int ldc, long long sC1, long long sC2,
    int K, int zdiv)
{
    __shared__ float As[16][132];
    __shared__ float Bs[16][64];
    int z = blockIdx.z, z1 = z / zdiv, z2 = z % zdiv;
    A += z1 * sA1 + z2 * sA2;
    B += z1 * sB1 + z2 * sB2;
    C += z1 * sC1 + z2 * sC2;
    const int m0 = blockIdx.x * 128;
    const int tid = threadIdx.x;
    const int tr = tid >> 4, tc = tid & 15;
    float acc[8][4];
    #pragma unroll
    for (int i = 0; i < 8; i++)
        #pragma unroll
        for (int j = 0; j < 4; j++) acc[i][j] = 0.f;

    for (int k0 = 0; k0 < K; k0 += 16) {
        #pragma unroll
        for (int rep = 0; rep < 2; rep++) {
            int v = rep * 256 + tid;
            int r = v >> 2, c4 = (v & 3) * 4;
            float4 ta = *reinterpret_cast<const float4*>(&A[(long long)(m0 + r) * lda + k0 + c4]);
            As[c4 + 0][r] = ta.x; As[c4 + 1][r] = ta.y; As[c4 + 2][r] = ta.z; As[c4 + 3][r] = ta.w;
        }
        {
            int r = tid >> 4, c4 = (tid & 15) * 4;
            *reinterpret_cast<float4*>(&Bs[r][c4]) =
                *reinterpret_cast<const float4*>(&B[(long long)(k0 + r) * ldb + c4]);
        }
        __syncthreads();
        #pragma unroll
        for (int kk = 0; kk < 16; kk++) {
            float a[8], b[4];
            *reinterpret_cast<float4*>(a)     = *reinterpret_cast<const float4*>(&As[kk][tr * 8]);
            *reinterpret_cast<float4*>(a + 4) = *reinterpret_cast<const float4*>(&As[kk][tr * 8 + 4]);
            *reinterpret_cast<float4*>(b)     = *reinterpret_cast<const float4*>(&Bs[kk][tc * 4]);
            #pragma unroll
            for (int i = 0; i < 8; i++)
                #pragma unroll
                for (int j = 0; j < 4; j++) acc[i][j] = fmaf(a[i], b[j], acc[i][j]);
        }
        __syncthreads();
    }
    #pragma unroll
    for (int i = 0; i < 8; i++) {
        int m = m0 + tr * 8 + i;
        float4 o;
        float* op = &o.x;
        #pragma unroll
        for (int j = 0; j < 4; j++) {
            float v = acc[i][j];
            op[j] = v / (1.f + __expf(-v));   // silu
        }
        *reinterpret_cast<float4*>(&C[(long long)m * ldc + tc * 4]) = o;
    }
}

// ---------------- small kernels ----------------
__global__ void k_colmean(const float* __restrict__ x, int lda) {
    int b = blockIdx.y;
    int c = blockIdx.x * 256 + threadIdx.x;
    const float* p = x + (long long)b * Tt * lda + c;
    float s = 0.f;
    for (int t = 0; t < Tt; t++) s += p[(long long)t * lda];
    g_mean[b * Cc + c] = s * (1.f / Tt);
}

__global__ void k_aware(const float* __restrict__ aw, const float* __restrict__ ab,
                        const float* __restrict__ ds) {
    int b = blockIdx.x >> 4, h = blockIdx.x & 15;
    const float* m = g_mean + b * Cc;
    const float* w = aw + h * Cc;
    float s = 0.f;
    for (int c = threadIdx.x; c < Cc; c += 256) s += m[c] * w[c];
    s = blockReduceSum(s);
    if (threadIdx.x == 0) g_scale[b * Hh + h] = ds[0] * (s + ab[h]);
}

__global__ void k_softmax_prior(int phase) {
    long long row = blockIdx.x;
    const float* s = g_scores + row * Tt;
    float* a = g_attn + row * Tt;
    int tid = threadIdx.x;
    float v[4];
    float mx = -1e30f;
    #pragma unroll
    for (int i = 0; i < 4; i++) { v[i] = s[tid + i * 256]; mx = fmaxf(mx, v[i]); }
    mx = blockReduceMax(mx);
    float sum = 0.f;
    #pragma unroll
    for (int i = 0; i < 4; i++) { v[i] = __expf(v[i] - mx); sum += v[i]; }
    sum = blockReduceSum(sum);
    float inv = 1.f / sum;
    #pragma unroll
    for (int i = 0; i < 4; i++) {
        float o = v[i] * inv;
        if (phase) o += 0.3f * a[tid + i * 256];
        a[tid + i * 256] = o;
    }
}

__global__ void k_layernorm(const float* __restrict__ gam, const float* __restrict__ bet,
                            float* __restrict__ out) {
    int row = blockIdx.x;
    const float* y = g_y + (long long)row * Cc;
    float s = 0.f, q = 0.f;
    for (int c = threadIdx.x; c < Cc; c += 256) { float v = y[c]; s += v; q += v * v; }
    s = blockReduceSum(s);
    q = blockReduceSum(q);
    float mu = s * (1.f / Cc);
    float var = q * (1.f / Cc) - mu * mu;
    float inv = rsqrtf(var + 1e-5f);
    for (int c = threadIdx.x; c < Cc; c += 256) {
        float xn = (y[c] - mu) * inv * gam[c] + bet[c];
        g_xn[(long long)row * Cc + c] = xn;
        out[(long long)row * Cc + c] = xn;
    }
}

__global__ void k_zero() { if (threadIdx.x < Ee) g_cursor[threadIdx.x] = 0; }

__global__ void k_gate(const float* __restrict__ gw) {
    int n = blockIdx.x;
    int wid = threadIdx.x >> 5, lane = threadIdx.x & 31;
    __shared__ float lg[Ee];
    const float* t = g_xn + (long long)n * Cc;
    const float* w = gw + wid * Cc;
    float s = 0.f;
    for (int c = lane; c < Cc; c += 32) s += t[c] * w[c];
    #pragma unroll
    for (int o = 16; o; o >>= 1) s += __shfl_xor_sync(0xffffffffu, s, o);
    if (lane == 0) lg[wid] = s;
    __syncthreads();
    if (threadIdx.x == 0) {
        float mx = lg[0];
        #pragma unroll
        for (int e = 1; e < Ee; e++) mx = fmaxf(mx, lg[e]);
        float p[Ee];
        #pragma unroll
        for (int e = 0; e < Ee; e++) p[e] = __expf(lg[e] - mx);
        int i1 = 0;
        #pragma unroll
        for (int e = 1; e < Ee; e++) if (p[e] > p[i1]) i1 = e;
        int i2 = (i1 == 0) ? 1 : 0;
        #pragma unroll
        for (int e = 0; e < Ee; e++) if (e != i1 && p[e] > p[i2]) i2 = e;
        float tot = p[i1] + p[i2];
        float w1 = p[i1] / tot, w2 = p[i2] / tot;
        int p1 = atomicAdd(&g_cursor[i1], 1);
        g_tok[i1 * NN + p1] = n; g_wgt[i1 * NN + p1] = w1;
        int p2 = atomicAdd(&g_cursor[i2], 1);
        g_tok[i2 * NN + p2] = n; g_wgt[i2 * NN + p2] = w2;
    }
}

// ---------------- gathered expert FC1 (with a = h^2 * sigmoid(h)) -----------
__global__ __launch_bounds__(256) void k_fc1(const float* __restrict__ fc1w,
                                             const float* __restrict__ fc1b) {
    int e = blockIdx.z;
    int cnt = g_cursor[e];
    int m0 = blockIdx.x * 128;
    if (m0 >= cnt) return;
    int n0 = blockIdx.y * 128;
    const float* Bw = fc1w + (long long)e * DFF * Cc;
    __shared__ float As[16][132];
    __shared__ float Bs[16][132];
    __shared__ int toks[128];
    int tid = threadIdx.x;
    if (tid < 128) {
        int m = m0 + tid;
        toks[tid] = (m < cnt) ? g_tok[e * NN + m] : -1;
    }
    __syncthreads();
    int tr = tid >> 4, tc = tid & 15;
    float acc[8][8];
    #pragma unroll
    for (int i = 0; i < 8; i++)
        #pragma unroll
        for (int j = 0; j < 8; j++) acc[i][j] = 0.f;

    for (int k0 = 0; k0 < Cc; k0 += 16) {
        #pragma unroll
        for (int rep = 0; rep < 2; rep++) {
            int v = rep * 256 + tid;
            int r = v >> 2, c4 = (v & 3) * 4;
            int tk = toks[r];
            float4 ta = (tk >= 0)
                ? *reinterpret_cast<const float4*>(&g_xn[(long long)tk * Cc + k0 + c4])
                : make_float4(0.f, 0.f, 0.f, 0.f);
            As[c4 + 0][r] = ta.x; As[c4 + 1][r] = ta.y; As[c4 + 2][r] = ta.z; As[c4 + 3][r] = ta.w;
            float4 tb = *reinterpret_cast<const float4*>(&Bw[(long long)(n0 + r) * Cc + k0 + c4]);
            Bs[c4 + 0][r] = tb.x; Bs[c4 + 1][r] = tb.y; Bs[c4 + 2][r] = tb.z; Bs[c4 + 3][r] = tb.w;
        }
        __syncthreads();
        #pragma unroll
        for (int kk = 0; kk < 16; kk++) {
            float a[8], b[8];
            *reinterpret_cast<float4*>(a)     = *reinterpret_cast<const float4*>(&As[kk][tr * 8]);
            *reinterpret_cast<float4*>(a + 4) = *reinterpret_cast<const float4*>(&As[kk][tr * 8 + 4]);
            *reinterpret_cast<float4*>(b)     = *reinterpret_cast<const float4*>(&Bs[kk][tc * 8]);
            *reinterpret_cast<float4*>(b + 4) = *reinterpret_cast<const float4*>(&Bs[kk][tc * 8 + 4]);
            #pragma unroll
            for (int i = 0; i < 8; i++)
                #pragma unroll
                for (int j = 0; j < 8; j++) acc[i][j] = fmaf(a[i], b[j], acc[i][j]);
        }
        __syncthreads();
    }
    const float* bp = fc1b + e * DFF;
    #pragma unroll
    for (int i = 0; i < 8; i++) {
        int m = m0 + tr * 8 + i;
        if (m < cnt) {
            #pragma unroll
            for (int j = 0; j < 8; j++) {
                int n = n0 + tc * 8 + j;
                float h = acc[i][j] + bp[n];
                // a = h * silu(h) = h^2 * sigmoid(h)
                g_act[((long long)e * NN + m) * DFF + n] = h * h / (1.f + __expf(-h));
            }
        }
    }
}

// ---------------- gathered expert FC2 + weighted scatter-add -----------------
__global__ __launch_bounds__(256) void k_fc2(const float* __restrict__ fc2w,
                                             const float* __restrict__ fc2b,
                                             float* __restrict__ out) {
    int e = blockIdx.z;
    int cnt = g_cursor[e];
    int m0 = blockIdx.x * 128;
    if (m0 >= cnt) return;
    int n0 = blockIdx.y * 128;
    const float* Aa = g_act + (long long)e * NN * DFF;
    const float* Bw = fc2w + (long long)e * Cc * DFF;
    __shared__ float As[16][132];
    __shared__ float Bs[16][132];
    int tid = threadIdx.x;
    int tr = tid >> 4, tc = tid & 15;
    float acc[8][8];
    #pragma unroll
    for (int i = 0; i < 8; i++)
        #pragma unroll
        for (int j = 0; j < 8; j++) acc[i][j] = 0.f;

    for (int k0 = 0; k0 < DFF; k0 += 16) {
        #pragma unroll
        for (int rep = 0; rep < 2; rep++) {
            int v = rep * 256 + tid;
            int r = v >> 2, c4 = (v & 3) * 4;
            float4 ta = (m0 + r < cnt)
                ? *reinterpret_cast<const float4*>(&Aa[(long long)(m0 + r) * DFF + k0 + c4])
                : make_float4(0.f, 0.f, 0.f, 0.f);
            As[c4 + 0][r] = ta.x; As[c4 + 1][r] = ta.y; As[c4 + 2][r] = ta.z; As[c4 + 3][r] = ta.w;
            float4 tb = *reinterpret_cast<const float4*>(&Bw[(long long)(n0 + r) * DFF + k0 + c4]);
            Bs[c4 + 0][r] = tb.x; Bs[c4 + 1][r] = tb.y; Bs[c4 + 2][r] = tb.z; Bs[c4 + 3][r] = tb.w;
        }
        __syncthreads();
        #pragma unroll
        for (int kk = 0; kk < 16; kk++) {
            float a[8], b[8];
            *reinterpret_cast<float4*>(a)     = *reinterpret_cast<const float4*>(&As[kk][tr * 8]);
            *reinterpret_cast<float4*>(a + 4) = *reinterpret_cast<const float4*>(&As[kk][tr * 8 + 4]);
            *reinterpret_cast<float4*>(b)     = *reinterpret_cast<const float4*>(&Bs[kk][tc * 8]);
            *reinterpret_cast<float4*>(b + 4) = *reinterpret_cast<const float4*>(&Bs[kk][tc * 8 + 4]);
            #pragma unroll
            for (int i = 0; i < 8; i++)
                #pragma unroll
                for (int j = 0; j < 8; j++) acc[i][j] = fmaf(a[i], b[j], acc[i][j]);
        }
        __syncthreads();
    }
    const float* bp = fc2b + e * Cc;
    #pragma unroll
    for (int i = 0; i < 8; i++) {
        int m = m0 + tr * 8 + i;
        if (m < cnt) {
            int tk = g_tok[e * NN + m];
            float w = g_wgt[e * NN + m] * 0.5f;   // * RATIO
            #pragma unroll
            for (int j = 0; j < 8; j++) {
                int n = n0 + tc * 8 + j;
                atomicAdd(&out[(long long)tk * Cc + n], (acc[i][j] + bp[n]) * w);
            }
        }
    }
}

// ---------------- launch ----------------
extern "C" void kernel_launch(void* const* d_in, const int* in_sizes, int n_in,
                              void* d_out, int out_size) {
    (void)in_sizes; (void)n_in; (void)out_size;
    const float* x       = (const float*)d_in[0];
    const float* qkv_w   = (const float*)d_in[1];
    const float* qkv_b   = (const float*)d_in[2];
    const float* aware_w = (const float*)d_in[3];
    const float* aware_b = (const float*)d_in[4];
    const float* dyn     = (const float*)d_in[5];
    const float* mw      = (const float*)d_in[6];
    const float* mb      = (const float*)d_in[7];
    const float* lng     = (const float*)d_in[8];
    const float* lnb     = (const float*)d_in[9];
    const float* gw      = (const float*)d_in[10];
    const float* f1w     = (const float*)d_in[11];
    const float* f1b     = (const float*)d_in[12];
    const float* f2w     = (const float*)d_in[13];
    const float* f2b     = (const float*)d_in[14];
    float* out = (float*)d_out;

    float *catp, *qkvp, *scoresp, *attnp, *yp, *scalep;
    cudaGetSymbolAddress((void**)&catp,    g_cat);
    cudaGetSymbolAddress((void**)&qkvp,    g_qkv);
    cudaGetSymbolAddress((void**)&scoresp, g_scores);
    cudaGetSymbolAddress((void**)&attnp,   g_attn);
    cudaGetSymbolAddress((void**)&yp,      g_y);
    cudaGetSymbolAddress((void**)&scalep,  g_scale);

    for (int i = 0; i < Pp; i++) {
        const float* xin = (i == 0) ? x : (catp + (i - 1) * Cc);
        int ldx = (i == 0) ? Cc : C3;

        k_colmean<<<dim3(Cc / 256, Bb), 256>>>(xin, ldx);
        k_aware<<<Bb * Hh, 256>>>(aware_w + (long long)i * Hh * Cc,
                                  aware_b + i * Hh, dyn + i);
        // qkv: (2048 x 1024) @ (3072 x 1024)^T + b -> g_qkv
        k_gemm_abT<<<dim3(NN / 128, C3 / 128, 1), 256>>>(
            xin, ldx, 0, 0,
            qkv_w + (long long)i * C3 * Cc, Cc, 0, 0,
            qkv_b + (long long)i * C3,
            qkvp, C3, 0, 0,
            Cc, 1, nullptr, nullptr, 0, 0);
        // scores: per (b,h): Q(1024x64) @ K^T, scaled by g_scale[z]
        k_gemm_abT<<<dim3(Tt / 128, Tt / 128, Bb * Hh), 256>>>(
            qkvp,       C3, (long long)Tt * C3, Dd,
            qkvp + Cc,  C3, (long long)Tt * C3, Dd,
            nullptr,
            scoresp, Tt, (long long)Hh * Tt * Tt, (long long)Tt * Tt,
            Dd, Hh, scalep, nullptr, 0, 0);
        // softmax + prior recurrence (writes g_attn)
        k_softmax_prior<<<Bb * Hh * Tt, 256>>>(i);
        // AV: attn(1024x1024) @ V(1024x64), silu, -> g_cat[:, i*C ...]
        k_gemm_ab_silu<<<dim3(Tt / 128, 1, Bb * Hh), 256>>>(
            attnp,          Tt, (long long)Hh * Tt * Tt, (long long)Tt * Tt,
            qkvp + 2 * Cc,  C3, (long long)Tt * C3, Dd,
            catp + i * Cc,  C3, (long long)Tt * C3, Dd,
            Tt, Hh);
    }

    // merger: (2048 x 3072) @ (1024 x 3072)^T + b + residual -> g_y
    k_gemm_abT<<<dim3(NN / 128, Cc / 128, 1), 256>>>(
        catp, C3, 0, 0,
        mw,   C3, 0, 0,
        mb,
        yp, Cc, 0, 0,
        C3, 1, nullptr, x, Cc, 0);

    k_layernorm<<<NN, 256>>>(lng, lnb, out);   // writes g_xn AND d_out=xn
    k_zero<<<1, 32>>>();
    k_gate<<<NN, 256>>>(gw);
    k_fc1<<<dim3(NN / 128, DFF / 128, Ee), 256>>>(f1w, f1b);
    k_fc2<<<dim3(NN / 128, Cc / 128, Ee), 256>>>(f2w, f2b, out);
}

// round 7
// speedup vs baseline: 1.4010x; 1.4010x over previous
#include <cuda_runtime.h>
#include <mma.h>
using namespace nvcuda;

#define Bb   2
#define Tt   1024
#define Cc   1024
#define Hh   16
#define Dd   64
#define Pp   3
#define Ee   8
#define DFF  1024
#define NN   (Bb*Tt)          // 2048 tokens
#define C3   (3*Cc)           // 3072

// ---------------- scratch (static device allocations) ----------------
__device__ float g_qkv[NN*C3];
__device__ float g_cat[NN*C3];
__device__ float g_scores[Bb*Hh*Tt*Tt];
__device__ float g_attn[Bb*Hh*Tt*Tt];
__device__ float g_y[NN*Cc];
__device__ float g_xn[NN*Cc];
__device__ float g_mean[Bb*Cc];
__device__ float g_scale[Bb*Hh];
__device__ int   g_cursor[Ee];
__device__ int   g_tok[Ee*NN];
__device__ float g_wgt[Ee*NN];
__device__ float g_act[Ee*NN*DFF];

typedef wmma::fragment<wmma::matrix_a, 16, 16, 8, wmma::precision::tf32, wmma::row_major> FragA;
typedef wmma::fragment<wmma::matrix_b, 16, 16, 8, wmma::precision::tf32, wmma::col_major> FragBc;
typedef wmma::fragment<wmma::matrix_b, 16, 16, 8, wmma::precision::tf32, wmma::row_major> FragBr;
typedef wmma::fragment<wmma::accumulator, 16, 16, 8, float> FragC;

template <class F>
__device__ __forceinline__ void cvt_frag(F& f) {
    #pragma unroll
    for (int t = 0; t < f.num_elements; t++) f.x[t] = wmma::__float_to_tf32(f.x[t]);
}

// ---------------- block reductions ----------------
__device__ __forceinline__ float blockReduceSum(float v) {
    __shared__ float sh[8];
    int lane = threadIdx.x & 31, w = threadIdx.x >> 5;
    #pragma unroll
    for (int o = 16; o; o >>= 1) v += __shfl_xor_sync(0xffffffffu, v, o);
    if (lane == 0) sh[w] = v;
    __syncthreads();
    float r = 0.f;
    #pragma unroll
    for (int i = 0; i < 8; i++) r += sh[i];
    __syncthreads();
    return r;
}
__device__ __forceinline__ float blockReduceMax(float v) {
    __shared__ float sh[8];
    int lane = threadIdx.x & 31, w = threadIdx.x >> 5;
    #pragma unroll
    for (int o = 16; o; o >>= 1) v = fmaxf(v, __shfl_xor_sync(0xffffffffu, v, o));
    if (lane == 0) sh[w] = v;
    __syncthreads();
    float r = -1e30f;
    #pragma unroll
    for (int i = 0; i < 8; i++) r = fmaxf(r, sh[i]);
    __syncthreads();
    return r;
}

// ========== generic C = A @ B^T, 128x128 tiles, wmma tf32 ==========
// 8 warps as 4x2: warp tile 32 rows x 64 cols = 2x4 wmma tiles (16x16).
// batched via z. epilogue: *scale_z[z], +bias[n], +addsrc[m,n], optional silu.
__global__ __launch_bounds__(256) void k_gemm_abT(
    const float* __restrict__ A, int lda, long long sA1, long long sA2,
    const float* __restrict__ B, int ldb, long long sB1, long long sB2,
    const float* __restrict__ bias,
    float* __restrict__ C, int ldc, long long sC1, long long sC2,
    int K, int zdiv,
    const float* __restrict__ scale_z,
    const float* __restrict__ addsrc, int ldadd,
    int act)
{
    __shared__ float As[128][20];
    __shared__ float Bs[128][20];
    int z = blockIdx.z, z1 = z / zdiv, z2 = z % zdiv;
    A += z1 * sA1 + z2 * sA2;
    B += z1 * sB1 + z2 * sB2;
    C += z1 * sC1 + z2 * sC2;
    const int m0 = blockIdx.x * 128, n0 = blockIdx.y * 128;
    const int tid = threadIdx.x, wid = tid >> 5, lane = tid & 31;
    const int mw = (wid >> 1) * 32, nw = (wid & 1) * 64;
    FragC acc[2][4];
    #pragma unroll
    for (int i = 0; i < 2; i++)
        #pragma unroll
        for (int j = 0; j < 4; j++) wmma::fill_fragment(acc[i][j], 0.f);

    for (int k0 = 0; k0 < K; k0 += 16) {
        #pragma unroll
        for (int rep = 0; rep < 2; rep++) {
            int v = rep * 256 + tid, r = v >> 2, c4 = (v & 3) * 4;
            *reinterpret_cast<float4*>(&As[r][c4]) =
                *reinterpret_cast<const float4*>(&A[(long long)(m0 + r) * lda + k0 + c4]);
            *reinterpret_cast<float4*>(&Bs[r][c4]) =
                *reinterpret_cast<const float4*>(&B[(long long)(n0 + r) * ldb + k0 + c4]);
        }
        __syncthreads();
        #pragma unroll
        for (int s = 0; s < 2; s++) {
            FragA af[2];
            FragBc bf[4];
            #pragma unroll
            for (int i = 0; i < 2; i++) {
                wmma::load_matrix_sync(af[i], &As[mw + i * 16][s * 8], 20);
                cvt_frag(af[i]);
            }
            #pragma unroll
            for (int j = 0; j < 4; j++) {
                wmma::load_matrix_sync(bf[j], &Bs[nw + j * 16][s * 8], 20);
                cvt_frag(bf[j]);
            }
            #pragma unroll
            for (int i = 0; i < 2; i++)
                #pragma unroll
                for (int j = 0; j < 4; j++)
                    wmma::mma_sync(acc[i][j], af[i], bf[j], acc[i][j]);
        }
        __syncthreads();
    }
    // epilogue via per-warp smem staging (reuse As)
    float sc = scale_z ? scale_z[z] : 1.f;
    float* stage = &As[0][0] + wid * 320;   // 16x20 per warp
    const int er = lane >> 1, ec0 = (lane & 1) * 8;
    #pragma unroll
    for (int i = 0; i < 2; i++) {
        #pragma unroll
        for (int j = 0; j < 4; j++) {
            wmma::store_matrix_sync(stage, acc[i][j], 20, wmma::mem_row_major);
            __syncwarp();
            int row = m0 + mw + i * 16 + er;
            int col = n0 + nw + j * 16 + ec0;
            float vals[8];
            #pragma unroll
            for (int q = 0; q < 8; q++) {
                float v = stage[er * 20 + ec0 + q] * sc;
                int nn = col + q;
                if (bias)   v += bias[nn];
                if (addsrc) v += addsrc[(long long)row * ldadd + nn];
                if (act)    v = v / (1.f + __expf(-v));
                vals[q] = v;
            }
            *reinterpret_cast<float4*>(&C[(long long)row * ldc + col]) =
                make_float4(vals[0], vals[1], vals[2], vals[3]);
            *reinterpret_cast<float4*>(&C[(long long)row * ldc + col + 4]) =
                make_float4(vals[4], vals[5], vals[6], vals[7]);
            __syncwarp();
        }
    }
}

// ========== C = A @ B (row-major B, N=64), silu epilogue (AV) ==========
// 8 warps as 4x2: warp tile 32x32 = 2x2 wmma tiles.
__global__ __launch_bounds__(256) void k_gemm_ab_silu(
    const float* __restrict__ A, int lda, long long sA1, long long sA2,
    const float* __restrict__ B, int ldb, long long sB1, long long sB2,
    float* __restrict__ C, int ldc, long long sC1, long long sC2,
    int K, int zdiv)
{
    __shared__ float As[128][20];
    __shared__ float Vs[16][72];
    int z = blockIdx.z, z1 = z / zdiv, z2 = z % zdiv;
    A += z1 * sA1 + z2 * sA2;
    B += z1 * sB1 + z2 * sB2;
    C += z1 * sC1 + z2 * sC2;
    const int m0 = blockIdx.x * 128;
    const int tid = threadIdx.x, wid = tid >> 5, lane = tid & 31;
    const int mw = (wid >> 1) * 32, nw = (wid & 1) * 32;
    FragC acc[2][2];
    #pragma unroll
    for (int i = 0; i < 2; i++)
        #pragma unroll
        for (int j = 0; j < 2; j++) wmma::fill_fragment(acc[i][j], 0.f);

    for (int k0 = 0; k0 < K; k0 += 16) {
        #pragma unroll
        for (int rep = 0; rep < 2; rep++) {
            int v = rep * 256 + tid, r = v >> 2, c4 = (v & 3) * 4;
            *reinterpret_cast<float4*>(&As[r][c4]) =
                *reinterpret_cast<const float4*>(&A[(long long)(m0 + r) * lda + k0 + c4]);
        }
        {
            int r = tid >> 4, c4 = (tid & 15) * 4;
            *reinterpret_cast<float4*>(&Vs[r][c4]) =
                *reinterpret_cast<const float4*>(&B[(long long)(k0 + r) * ldb + c4]);
        }
        __syncthreads();
        #pragma unroll
        for (int s = 0; s < 2; s++) {
            FragA af[2];
            FragBr bf[2];
            #pragma unroll
            for (int i = 0; i < 2; i++) {
                wmma::load_matrix_sync(af[i], &As[mw + i * 16][s * 8], 20);
                cvt_frag(af[i]);
            }
            #pragma unroll
            for (int j = 0; j < 2; j++) {
                wmma::load_matrix_sync(bf[j], &Vs[s * 8][nw + j * 16], 72);
                cvt_frag(bf[j]);
            }
            #pragma unroll
            for (int i = 0; i < 2; i++)
                #pragma unroll
                for (int j = 0; j < 2; j++)
                    wmma::mma_sync(acc[i][j], af[i], bf[j], acc[i][j]);
        }
        __syncthreads();
    }
    float* stage = &As[0][0] + wid * 320;
    const int er = lane >> 1, ec0 = (lane & 1) * 8;
    #pragma unroll
    for (int i = 0; i < 2; i++) {
        #pragma unroll
        for (int j = 0; j < 2; j++) {
            wmma::store_matrix_sync(stage, acc[i][j], 20, wmma::mem_row_major);
            __syncwarp();
            int row = m0 + mw + i * 16 + er;
            int col = nw + j * 16 + ec0;
            float vals[8];
            #pragma unroll
            for (int q = 0; q < 8; q++) {
                float v = stage[er * 20 + ec0 + q];
                vals[q] = v / (1.f + __expf(-v));
            }
            *reinterpret_cast<float4*>(&C[(long long)row * ldc + col]) =
                make_float4(vals[0], vals[1], vals[2], vals[3]);
            *reinterpret_cast<float4*>(&C[(long long)row * ldc + col + 4]) =
                make_float4(vals[4], vals[5], vals[6], vals[7]);
            __syncwarp();
        }
    }
}

// ---------------- small kernels ----------------
__global__ void k_colmean(const float* __restrict__ x, int lda) {
    int b = blockIdx.y;
    int c = blockIdx.x * 256 + threadIdx.x;
    const float* p = x + (long long)b * Tt * lda + c;
    float s = 0.f;
    for (int t = 0; t < Tt; t++) s += p[(long long)t * lda];
    g_mean[b * Cc + c] = s * (1.f / Tt);
}

__global__ void k_aware(const float* __restrict__ aw, const float* __restrict__ ab,
                        const float* __restrict__ ds) {
    int b = blockIdx.x >> 4, h = blockIdx.x & 15;
    const float* m = g_mean + b * Cc;
    const float* w = aw + h * Cc;
    float s = 0.f;
    for (int c = threadIdx.x; c < Cc; c += 256) s += m[c] * w[c];
    s = blockReduceSum(s);
    if (threadIdx.x == 0) g_scale[b * Hh + h] = ds[0] * (s + ab[h]);
}

__global__ void k_softmax_prior(int phase) {
    long long row = blockIdx.x;
    const float* s = g_scores + row * Tt;
    float* a = g_attn + row * Tt;
    int tid = threadIdx.x;
    float v[4];
    float mx = -1e30f;
    #pragma unroll
    for (int i = 0; i < 4; i++) { v[i] = s[tid + i * 256]; mx = fmaxf(mx, v[i]); }
    mx = blockReduceMax(mx);
    float sum = 0.f;
    #pragma unroll
    for (int i = 0; i < 4; i++) { v[i] = __expf(v[i] - mx); sum += v[i]; }
    sum = blockReduceSum(sum);
    float inv = 1.f / sum;
    #pragma unroll
    for (int i = 0; i < 4; i++) {
        float o = v[i] * inv;
        if (phase) o += 0.3f * a[tid + i * 256];
        a[tid + i * 256] = o;
    }
}

__global__ void k_layernorm(const float* __restrict__ gam, const float* __restrict__ bet,
                            float* __restrict__ out) {
    int row = blockIdx.x;
    const float* y = g_y + (long long)row * Cc;
    float s = 0.f, q = 0.f;
    for (int c = threadIdx.x; c < Cc; c += 256) { float v = y[c]; s += v; q += v * v; }
    s = blockReduceSum(s);
    q = blockReduceSum(q);
    float mu = s * (1.f / Cc);
    float var = q * (1.f / Cc) - mu * mu;
    float inv = rsqrtf(var + 1e-5f);
    for (int c = threadIdx.x; c < Cc; c += 256) {
        float xn = (y[c] - mu) * inv * gam[c] + bet[c];
        g_xn[(long long)row * Cc + c] = xn;
        out[(long long)row * Cc + c] = xn;
    }
}

__global__ void k_zero() { if (threadIdx.x < Ee) g_cursor[threadIdx.x] = 0; }

__global__ void k_gate(const float* __restrict__ gw) {
    int n = blockIdx.x;
    int wid = threadIdx.x >> 5, lane = threadIdx.x & 31;
    __shared__ float lg[Ee];
    const float* t = g_xn + (long long)n * Cc;
    const float* w = gw + wid * Cc;
    float s = 0.f;
    for (int c = lane; c < Cc; c += 32) s += t[c] * w[c];
    #pragma unroll
    for (int o = 16; o; o >>= 1) s += __shfl_xor_sync(0xffffffffu, s, o);
    if (lane == 0) lg[wid] = s;
    __syncthreads();
    if (threadIdx.x == 0) {
        float mx = lg[0];
        #pragma unroll
        for (int e = 1; e < Ee; e++) mx = fmaxf(mx, lg[e]);
        float p[Ee];
        #pragma unroll
        for (int e = 0; e < Ee; e++) p[e] = __expf(lg[e] - mx);
        int i1 = 0;
        #pragma unroll
        for (int e = 1; e < Ee; e++) if (p[e] > p[i1]) i1 = e;
        int i2 = (i1 == 0) ? 1 : 0;
        #pragma unroll
        for (int e = 0; e < Ee; e++) if (e != i1 && p[e] > p[i2]) i2 = e;
        float tot = p[i1] + p[i2];
        float w1 = p[i1] / tot, w2 = p[i2] / tot;
        int p1 = atomicAdd(&g_cursor[i1], 1);
        g_tok[i1 * NN + p1] = n; g_wgt[i1 * NN + p1] = w1;
        int p2 = atomicAdd(&g_cursor[i2], 1);
        g_tok[i2 * NN + p2] = n; g_wgt[i2 * NN + p2] = w2;
    }
}

// ========== gathered expert FC1, wmma tf32, a = h^2 * sigmoid(h) ==========
__global__ __launch_bounds__(256) void k_fc1(const float* __restrict__ fc1w,
                                             const float* __restrict__ fc1b) {
    int e = blockIdx.z;
    int cnt = g_cursor[e];
    int m0 = blockIdx.x * 128;
    if (m0 >= cnt) return;
    int n0 = blockIdx.y * 128;
    const float* Bw = fc1w + (long long)e * DFF * Cc;
    __shared__ float As[128][20];
    __shared__ float Bs[128][20];
    __shared__ int toks[128];
    const int tid = threadIdx.x, wid = tid >> 5, lane = tid & 31;
    const int mw = (wid >> 1) * 32, nw = (wid & 1) * 64;
    if (tid < 128) {
        int m = m0 + tid;
        toks[tid] = (m < cnt) ? g_tok[e * NN + m] : -1;
    }
    __syncthreads();
    FragC acc[2][4];
    #pragma unroll
    for (int i = 0; i < 2; i++)
        #pragma unroll
        for (int j = 0; j < 4; j++) wmma::fill_fragment(acc[i][j], 0.f);

    for (int k0 = 0; k0 < Cc; k0 += 16) {
        #pragma unroll
        for (int rep = 0; rep < 2; rep++) {
            int v = rep * 256 + tid, r = v >> 2, c4 = (v & 3) * 4;
            int tk = toks[r];
            float4 ta = (tk >= 0)
                ? *reinterpret_cast<const float4*>(&g_xn[(long long)tk * Cc + k0 + c4])
                : make_float4(0.f, 0.f, 0.f, 0.f);
            *reinterpret_cast<float4*>(&As[r][c4]) = ta;
            *reinterpret_cast<float4*>(&Bs[r][c4]) =
                *reinterpret_cast<const float4*>(&Bw[(long long)(n0 + r) * Cc + k0 + c4]);
        }
        __syncthreads();
        #pragma unroll
        for (int s = 0; s < 2; s++) {
            FragA af[2];
            FragBc bf[4];
            #pragma unroll
            for (int i = 0; i < 2; i++) {
                wmma::load_matrix_sync(af[i], &As[mw + i * 16][s * 8], 20);
                cvt_frag(af[i]);
            }
            #pragma unroll
            for (int j = 0; j < 4; j++) {
                wmma::load_matrix_sync(bf[j], &Bs[nw + j * 16][s * 8], 20);
                cvt_frag(bf[j]);
            }
            #pragma unroll
            for (int i = 0; i < 2; i++)
                #pragma unroll
                for (int j = 0; j < 4; j++)
                    wmma::mma_sync(acc[i][j], af[i], bf[j], acc[i][j]);
        }
        __syncthreads();
    }
    const float* bp = fc1b + e * DFF;
    float* stage = &As[0][0] + wid * 320;
    const int er = lane >> 1, ec0 = (lane & 1) * 8;
    #pragma unroll
    for (int i = 0; i < 2; i++) {
        #pragma unroll
        for (int j = 0; j < 4; j++) {
            wmma::store_matrix_sync(stage, acc[i][j], 20, wmma::mem_row_major);
            __syncwarp();
            int m = m0 + mw + i * 16 + er;
            if (m < cnt) {
                int n = n0 + nw + j * 16 + ec0;
                float vals[8];
                #pragma unroll
                for (int q = 0; q < 8; q++) {
                    float h = stage[er * 20 + ec0 + q] + bp[n + q];
                    vals[q] = h * h / (1.f + __expf(-h));   // h * silu(h)
                }
                float* op = &g_act[((long long)e * NN + m) * DFF + n];
                *reinterpret_cast<float4*>(op) = make_float4(vals[0], vals[1], vals[2], vals[3]);
                *reinterpret_cast<float4*>(op + 4) = make_float4(vals[4], vals[5], vals[6], vals[7]);
            }
            __syncwarp();
        }
    }
}

// ========== gathered expert FC2 + weighted scatter-add, wmma tf32 ==========
__global__ __launch_bounds__(256) void k_fc2(const float* __restrict__ fc2w,
                                             const float* __restrict__ fc2b,
                                             float* __restrict__ out) {
    int e = blockIdx.z;
    int cnt = g_cursor[e];
    int m0 = blockIdx.x * 128;
    if (m0 >= cnt) return;
    int n0 = blockIdx.y * 128;
    const float* Aa = g_act + (long long)e * NN * DFF;
    const float* Bw = fc2w + (long long)e * Cc * DFF;
    __shared__ float As[128][20];
    __shared__ float Bs[128][20];
    const int tid = threadIdx.x, wid = tid >> 5, lane = tid & 31;
    const int mw = (wid >> 1) * 32, nw = (wid & 1) * 64;
    FragC acc[2][4];
    #pragma unroll
    for (int i = 0; i < 2; i++)
        #pragma unroll
        for (int j = 0; j < 4; j++) wmma::fill_fragment(acc[i][j], 0.f);

    for (int k0 = 0; k0 < DFF; k0 += 16) {
        #pragma unroll
        for (int rep = 0; rep < 2; rep++) {
            int v = rep * 256 + tid, r = v >> 2, c4 = (v & 3) * 4;
            float4 ta = (m0 + r < cnt)
                ? *reinterpret_cast<const float4*>(&Aa[(long long)(m0 + r) * DFF + k0 + c4])
                : make_float4(0.f, 0.f, 0.f, 0.f);
            *reinterpret_cast<float4*>(&As[r][c4]) = ta;
            *reinterpret_cast<float4*>(&Bs[r][c4]) =
                *reinterpret_cast<const float4*>(&Bw[(long long)(n0 + r) * DFF + k0 + c4]);
        }
        __syncthreads();
        #pragma unroll
        for (int s = 0; s < 2; s++) {
            FragA af[2];
            FragBc bf[4];
            #pragma unroll
            for (int i = 0; i < 2; i++) {
                wmma::load_matrix_sync(af[i], &As[mw + i * 16][s * 8], 20);
                cvt_frag(af[i]);
            }
            #pragma unroll
            for (int j = 0; j < 4; j++) {
                wmma::load_matrix_sync(bf[j], &Bs[nw + j * 16][s * 8], 20);
                cvt_frag(bf[j]);
            }
            #pragma unroll
            for (int i = 0; i < 2; i++)
                #pragma unroll
                for (int j = 0; j < 4; j++)
                    wmma::mma_sync(acc[i][j], af[i], bf[j], acc[i][j]);
        }
        __syncthreads();
    }
    const float* bp = fc2b + e * Cc;
    float* stage = &As[0][0] + wid * 320;
    const int er = lane >> 1, ec0 = (lane & 1) * 8;
    #pragma unroll
    for (int i = 0; i < 2; i++) {
        #pragma unroll
        for (int j = 0; j < 4; j++) {
            wmma::store_matrix_sync(stage, acc[i][j], 20, wmma::mem_row_major);
            __syncwarp();
            int m = m0 + mw + i * 16 + er;
            if (m < cnt) {
                int tk = g_tok[e * NN + m];
                float w = g_wgt[e * NN + m] * 0.5f;   // * RATIO
                int n = n0 + nw + j * 16 + ec0;
                #pragma unroll
                for (int q = 0; q < 8; q++) {
                    atomicAdd(&out[(long long)tk * Cc + n + q],
                              (stage[er * 20 + ec0 + q] + bp[n + q]) * w);
                }
            }
            __syncwarp();
        }
    }
}

// ---------------- launch ----------------
extern "C" void kernel_launch(void* const* d_in, const int* in_sizes, int n_in,
                              void* d_out, int out_size) {
    (void)in_sizes; (void)n_in; (void)out_size;
    const float* x       = (const float*)d_in[0];
    const float* qkv_w   = (const float*)d_in[1];
    const float* qkv_b   = (const float*)d_in[2];
    const float* aware_w = (const float*)d_in[3];
    const float* aware_b = (const float*)d_in[4];
    const float* dyn     = (const float*)d_in[5];
    const float* mw      = (const float*)d_in[6];
    const float* mb      = (const float*)d_in[7];
    const float* lng     = (const float*)d_in[8];
    const float* lnb     = (const float*)d_in[9];
    const float* gw      = (const float*)d_in[10];
    const float* f1w     = (const float*)d_in[11];
    const float* f1b     = (const float*)d_in[12];
    const float* f2w     = (const float*)d_in[13];
    const float* f2b     = (const float*)d_in[14];
    float* out = (float*)d_out;

    float *catp, *qkvp, *scoresp, *attnp, *yp, *scalep;
    cudaGetSymbolAddress((void**)&catp,    g_cat);
    cudaGetSymbolAddress((void**)&qkvp,    g_qkv);
    cudaGetSymbolAddress((void**)&scoresp, g_scores);
    cudaGetSymbolAddress((void**)&attnp,   g_attn);
    cudaGetSymbolAddress((void**)&yp,      g_y);
    cudaGetSymbolAddress((void**)&scalep,  g_scale);

    for (int i = 0; i < Pp; i++) {
        const float* xin = (i == 0) ? x : (catp + (i - 1) * Cc);
        int ldx = (i == 0) ? Cc : C3;

        k_colmean<<<dim3(Cc / 256, Bb), 256>>>(xin, ldx);
        k_aware<<<Bb * Hh, 256>>>(aware_w + (long long)i * Hh * Cc,
                                  aware_b + i * Hh, dyn + i);
        // qkv: (2048 x 1024) @ (3072 x 1024)^T + b -> g_qkv
        k_gemm_abT<<<dim3(NN / 128, C3 / 128, 1), 256>>>(
            xin, ldx, 0, 0,
            qkv_w + (long long)i * C3 * Cc, Cc, 0, 0,
            qkv_b + (long long)i * C3,
            qkvp, C3, 0, 0,
            Cc, 1, nullptr, nullptr, 0, 0);
        // scores: per (b,h): Q(1024x64) @ K^T, scaled by g_scale[z]
        k_gemm_abT<<<dim3(Tt / 128, Tt / 128, Bb * Hh), 256>>>(
            qkvp,       C3, (long long)Tt * C3, Dd,
            qkvp + Cc,  C3, (long long)Tt * C3, Dd,
            nullptr,
            scoresp, Tt, (long long)Hh * Tt * Tt, (long long)Tt * Tt,
            Dd, Hh, scalep, nullptr, 0, 0);
        // softmax + prior recurrence (writes g_attn)
        k_softmax_prior<<<Bb * Hh * Tt, 256>>>(i);
        // AV: attn(1024x1024) @ V(1024x64), silu, -> g_cat[:, i*C ...]
        k_gemm_ab_silu<<<dim3(Tt / 128, 1, Bb * Hh), 256>>>(
            attnp,          Tt, (long long)Hh * Tt * Tt, (long long)Tt * Tt,
            qkvp + 2 * Cc,  C3, (long long)Tt * C3, Dd,
            catp + i * Cc,  C3, (long long)Tt * C3, Dd,
            Tt, Hh);
    }

    // merger: (2048 x 3072) @ (1024 x 3072)^T + b + residual -> g_y
    k_gemm_abT<<<dim3(NN / 128, Cc / 128, 1), 256>>>(
        catp, C3, 0, 0,
        mw,   C3, 0, 0,
        mb,
        yp, Cc, 0, 0,
        C3, 1, nullptr, x, Cc, 0);

    k_layernorm<<<NN, 256>>>(lng, lnb, out);   // writes g_xn AND d_out=xn
    k_zero<<<1, 32>>>();
    k_gate<<<NN, 256>>>(gw);
    k_fc1<<<dim3(NN / 128, DFF / 128, Ee), 256>>>(f1w, f1b);
    k_fc2<<<dim3(NN / 128, Cc / 128, Ee), 256>>>(f2w, f2b, out);
}

// round 8
// speedup vs baseline: 1.6121x; 1.1507x over previous
#include <cuda_runtime.h>
#include <mma.h>
using namespace nvcuda;

#define Bb   2
#define Tt   1024
#define Cc   1024
#define Hh   16
#define Dd   64
#define Pp   3
#define Ee   8
#define DFF  1024
#define NN   (Bb*Tt)          // 2048 tokens
#define C3   (3*Cc)           // 3072

// ---------------- scratch (static device allocations) ----------------
__device__ float g_qkv[NN*C3];
__device__ float g_cat[NN*C3];
__device__ float g_scores[Bb*Hh*Tt*Tt];
__device__ float g_attn[Bb*Hh*Tt*Tt];
__device__ float g_y[NN*Cc];
__device__ float g_xn[NN*Cc];
__device__ float g_mean[Bb*Cc];
__device__ float g_scale[Bb*Hh];
__device__ int   g_cursor[Ee];
__device__ int   g_tok[Ee*NN];
__device__ float g_wgt[Ee*NN];
__device__ float g_act[Ee*NN*DFF];

typedef wmma::fragment<wmma::matrix_a, 16, 16, 8, wmma::precision::tf32, wmma::row_major> FragA;
typedef wmma::fragment<wmma::matrix_b, 16, 16, 8, wmma::precision::tf32, wmma::col_major> FragBc;
typedef wmma::fragment<wmma::matrix_b, 16, 16, 8, wmma::precision::tf32, wmma::row_major> FragBr;
typedef wmma::fragment<wmma::accumulator, 16, 16, 8, float> FragC;

// NOTE: no tf32 cvt — HMMA.tf32 reads only the high bits (implicit truncation).

// ---------------- cp.async helpers ----------------
__device__ __forceinline__ void cp16(void* dst, const void* src) {
    unsigned ds = (unsigned)__cvta_generic_to_shared(dst);
    asm volatile("cp.async.cg.shared.global [%0], [%1], 16;" :: "r"(ds), "l"(src));
}
__device__ __forceinline__ void cp16p(void* dst, const void* src, bool pred) {
    unsigned ds = (unsigned)__cvta_generic_to_shared(dst);
    int sz = pred ? 16 : 0;
    asm volatile("cp.async.cg.shared.global [%0], [%1], 16, %2;" :: "r"(ds), "l"(src), "r"(sz));
}
#define CPCOMMIT asm volatile("cp.async.commit_group;")
#define CPWAIT0  asm volatile("cp.async.wait_group 0;")
#define CPWAIT1  asm volatile("cp.async.wait_group 1;")

// ---------------- block reductions ----------------
__device__ __forceinline__ float blockReduceSum(float v) {
    __shared__ float sh[8];
    int lane = threadIdx.x & 31, w = threadIdx.x >> 5;
    #pragma unroll
    for (int o = 16; o; o >>= 1) v += __shfl_xor_sync(0xffffffffu, v, o);
    if (lane == 0) sh[w] = v;
    __syncthreads();
    float r = 0.f;
    #pragma unroll
    for (int i = 0; i < 8; i++) r += sh[i];
    __syncthreads();
    return r;
}
__device__ __forceinline__ float blockReduceMax(float v) {
    __shared__ float sh[8];
    int lane = threadIdx.x & 31, w = threadIdx.x >> 5;
    #pragma unroll
    for (int o = 16; o; o >>= 1) v = fmaxf(v, __shfl_xor_sync(0xffffffffu, v, o));
    if (lane == 0) sh[w] = v;
    __syncthreads();
    float r = -1e30f;
    #pragma unroll
    for (int i = 0; i < 8; i++) r = fmaxf(r, sh[i]);
    __syncthreads();
    return r;
}

// ========== generic C = A @ B^T, 128x128 tiles, wmma tf32, 2-stage cp.async ==========
__global__ __launch_bounds__(256) void k_gemm_abT(
    const float* __restrict__ A, int lda, long long sA1, long long sA2,
    const float* __restrict__ B, int ldb, long long sB1, long long sB2,
    const float* __restrict__ bias,
    float* __restrict__ C, int ldc, long long sC1, long long sC2,
    int K, int zdiv,
    const float* __restrict__ scale_z,
    const float* __restrict__ addsrc, int ldadd,
    int act)
{
    __shared__ float As[2][128][20];
    __shared__ float Bs[2][128][20];
    int z = blockIdx.z, z1 = z / zdiv, z2 = z % zdiv;
    A += z1 * sA1 + z2 * sA2;
    B += z1 * sB1 + z2 * sB2;
    C += z1 * sC1 + z2 * sC2;
    const int m0 = blockIdx.x * 128, n0 = blockIdx.y * 128;
    const int tid = threadIdx.x, wid = tid >> 5, lane = tid & 31;
    const int mw = (wid >> 1) * 32, nw = (wid & 1) * 64;
    const int lr = tid >> 2, lc4 = (tid & 3) * 4;          // load map: 2 reps

    FragC acc[2][4];
    #pragma unroll
    for (int i = 0; i < 2; i++)
        #pragma unroll
        for (int j = 0; j < 4; j++) wmma::fill_fragment(acc[i][j], 0.f);

    const int nIter = K / 16;
    // prologue: tiles 0 and 1
    #pragma unroll
    for (int p = 0; p < 2; p++) {
        if (p < nIter) {
            int k0 = p * 16;
            #pragma unroll
            for (int rep = 0; rep < 2; rep++) {
                int r = lr + rep * 64;
                cp16(&As[p][r][lc4], &A[(long long)(m0 + r) * lda + k0 + lc4]);
                cp16(&Bs[p][r][lc4], &B[(long long)(n0 + r) * ldb + k0 + lc4]);
            }
            CPCOMMIT;
        }
    }
    for (int i = 0; i < nIter; i++) {
        if (i + 1 < nIter) { CPWAIT1; } else { CPWAIT0; }
        __syncthreads();
        int cur = i & 1;
        #pragma unroll
        for (int s = 0; s < 2; s++) {
            FragA af[2];
            FragBc bf[4];
            #pragma unroll
            for (int ii = 0; ii < 2; ii++)
                wmma::load_matrix_sync(af[ii], &As[cur][mw + ii * 16][s * 8], 20);
            #pragma unroll
            for (int j = 0; j < 4; j++)
                wmma::load_matrix_sync(bf[j], &Bs[cur][nw + j * 16][s * 8], 20);
            #pragma unroll
            for (int ii = 0; ii < 2; ii++)
                #pragma unroll
                for (int j = 0; j < 4; j++)
                    wmma::mma_sync(acc[ii][j], af[ii], bf[j], acc[ii][j]);
        }
        __syncthreads();
        if (i + 2 < nIter) {
            int k0 = (i + 2) * 16;
            #pragma unroll
            for (int rep = 0; rep < 2; rep++) {
                int r = lr + rep * 64;
                cp16(&As[cur][r][lc4], &A[(long long)(m0 + r) * lda + k0 + lc4]);
                cp16(&Bs[cur][r][lc4], &B[(long long)(n0 + r) * ldb + k0 + lc4]);
            }
            CPCOMMIT;
        }
    }
    // epilogue via per-warp smem staging (reuse As)
    float sc = scale_z ? scale_z[z] : 1.f;
    float* stage = &As[0][0][0] + wid * 320;   // 16x20 per warp
    const int er = lane >> 1, ec0 = (lane & 1) * 8;
    #pragma unroll
    for (int i = 0; i < 2; i++) {
        #pragma unroll
        for (int j = 0; j < 4; j++) {
            wmma::store_matrix_sync(stage, acc[i][j], 20, wmma::mem_row_major);
            __syncwarp();
            int row = m0 + mw + i * 16 + er;
            int col = n0 + nw + j * 16 + ec0;
            float vals[8];
            #pragma unroll
            for (int q = 0; q < 8; q++) {
                float v = stage[er * 20 + ec0 + q] * sc;
                int nn = col + q;
                if (bias)   v += bias[nn];
                if (addsrc) v += addsrc[(long long)row * ldadd + nn];
                if (act)    v = v / (1.f + __expf(-v));
                vals[q] = v;
            }
            *reinterpret_cast<float4*>(&C[(long long)row * ldc + col]) =
                make_float4(vals[0], vals[1], vals[2], vals[3]);
            *reinterpret_cast<float4*>(&C[(long long)row * ldc + col + 4]) =
                make_float4(vals[4], vals[5], vals[6], vals[7]);
            __syncwarp();
        }
    }
}

// ========== C = A @ B (row-major B, N=64), silu epilogue (AV) ==========
__global__ __launch_bounds__(256) void k_gemm_ab_silu(
    const float* __restrict__ A, int lda, long long sA1, long long sA2,
    const float* __restrict__ B, int ldb, long long sB1, long long sB2,
    float* __restrict__ C, int ldc, long long sC1, long long sC2,
    int K, int zdiv)
{
    __shared__ float As[2][128][20];
    __shared__ float Vs[2][16][68];
    int z = blockIdx.z, z1 = z / zdiv, z2 = z % zdiv;
    A += z1 * sA1 + z2 * sA2;
    B += z1 * sB1 + z2 * sB2;
    C += z1 * sC1 + z2 * sC2;
    const int m0 = blockIdx.x * 128;
    const int tid = threadIdx.x, wid = tid >> 5, lane = tid & 31;
    const int mw = (wid >> 1) * 32, nw = (wid & 1) * 32;
    const int lr = tid >> 2, lc4 = (tid & 3) * 4;
    const int vr = tid >> 4, vc4 = (tid & 15) * 4;

    FragC acc[2][2];
    #pragma unroll
    for (int i = 0; i < 2; i++)
        #pragma unroll
        for (int j = 0; j < 2; j++) wmma::fill_fragment(acc[i][j], 0.f);

    const int nIter = K / 16;
    #pragma unroll
    for (int p = 0; p < 2; p++) {
        if (p < nIter) {
            int k0 = p * 16;
            #pragma unroll
            for (int rep = 0; rep < 2; rep++) {
                int r = lr + rep * 64;
                cp16(&As[p][r][lc4], &A[(long long)(m0 + r) * lda + k0 + lc4]);
            }
            cp16(&Vs[p][vr][vc4], &B[(long long)(k0 + vr) * ldb + vc4]);
            CPCOMMIT;
        }
    }
    for (int i = 0; i < nIter; i++) {
        if (i + 1 < nIter) { CPWAIT1; } else { CPWAIT0; }
        __syncthreads();
        int cur = i & 1;
        #pragma unroll
        for (int s = 0; s < 2; s++) {
            FragA af[2];
            FragBr bf[2];
            #pragma unroll
            for (int ii = 0; ii < 2; ii++)
                wmma::load_matrix_sync(af[ii], &As[cur][mw + ii * 16][s * 8], 20);
            #pragma unroll
            for (int j = 0; j < 2; j++)
                wmma::load_matrix_sync(bf[j], &Vs[cur][s * 8][nw + j * 16], 68);
            #pragma unroll
            for (int ii = 0; ii < 2; ii++)
                #pragma unroll
                for (int j = 0; j < 2; j++)
                    wmma::mma_sync(acc[ii][j], af[ii], bf[j], acc[ii][j]);
        }
        __syncthreads();
        if (i + 2 < nIter) {
            int k0 = (i + 2) * 16;
            #pragma unroll
            for (int rep = 0; rep < 2; rep++) {
                int r = lr + rep * 64;
                cp16(&As[cur][r][lc4], &A[(long long)(m0 + r) * lda + k0 + lc4]);
            }
            cp16(&Vs[cur][vr][vc4], &B[(long long)(k0 + vr) * ldb + vc4]);
            CPCOMMIT;
        }
    }
    float* stage = &As[0][0][0] + wid * 320;
    const int er = lane >> 1, ec0 = (lane & 1) * 8;
    #pragma unroll
    for (int i = 0; i < 2; i++) {
        #pragma unroll
        for (int j = 0; j < 2; j++) {
            wmma::store_matrix_sync(stage, acc[i][j], 20, wmma::mem_row_major);
            __syncwarp();
            int row = m0 + mw + i * 16 + er;
            int col = nw + j * 16 + ec0;
            float vals[8];
            #pragma unroll
            for (int q = 0; q < 8; q++) {
                float v = stage[er * 20 + ec0 + q];
                vals[q] = v / (1.f + __expf(-v));
            }
            *reinterpret_cast<float4*>(&C[(long long)row * ldc + col]) =
                make_float4(vals[0], vals[1], vals[2], vals[3]);
            *reinterpret_cast<float4*>(&C[(long long)row * ldc + col + 4]) =
                make_float4(vals[4], vals[5], vals[6], vals[7]);
            __syncwarp();
        }
    }
}

// ---------------- small kernels ----------------
__global__ void k_colmean(const float* __restrict__ x, int lda) {
    int b = blockIdx.y;
    int c = blockIdx.x * 256 + threadIdx.x;
    const float* p = x + (long long)b * Tt * lda + c;
    float s = 0.f;
    for (int t = 0; t < Tt; t++) s += p[(long long)t * lda];
    g_mean[b * Cc + c] = s * (1.f / Tt);
}

__global__ void k_aware(const float* __restrict__ aw, const float* __restrict__ ab,
                        const float* __restrict__ ds) {
    int b = blockIdx.x >> 4, h = blockIdx.x & 15;
    const float* m = g_mean + b * Cc;
    const float* w = aw + h * Cc;
    float s = 0.f;
    for (int c = threadIdx.x; c < Cc; c += 256) s += m[c] * w[c];
    s = blockReduceSum(s);
    if (threadIdx.x == 0) g_scale[b * Hh + h] = ds[0] * (s + ab[h]);
}

__global__ void k_softmax_prior(int phase) {
    long long row = blockIdx.x;
    const float* s = g_scores + row * Tt;
    float* a = g_attn + row * Tt;
    int tid = threadIdx.x;
    float v[4];
    float mx = -1e30f;
    #pragma unroll
    for (int i = 0; i < 4; i++) { v[i] = s[tid + i * 256]; mx = fmaxf(mx, v[i]); }
    mx = blockReduceMax(mx);
    float sum = 0.f;
    #pragma unroll
    for (int i = 0; i < 4; i++) { v[i] = __expf(v[i] - mx); sum += v[i]; }
    sum = blockReduceSum(sum);
    float inv = 1.f / sum;
    #pragma unroll
    for (int i = 0; i < 4; i++) {
        float o = v[i] * inv;
        if (phase) o += 0.3f * a[tid + i * 256];
        a[tid + i * 256] = o;
    }
}

__global__ void k_layernorm(const float* __restrict__ gam, const float* __restrict__ bet,
                            float* __restrict__ out) {
    int row = blockIdx.x;
    const float* y = g_y + (long long)row * Cc;
    float s = 0.f, q = 0.f;
    for (int c = threadIdx.x; c < Cc; c += 256) { float v = y[c]; s += v; q += v * v; }
    s = blockReduceSum(s);
    q = blockReduceSum(q);
    float mu = s * (1.f / Cc);
    float var = q * (1.f / Cc) - mu * mu;
    float inv = rsqrtf(var + 1e-5f);
    for (int c = threadIdx.x; c < Cc; c += 256) {
        float xn = (y[c] - mu) * inv * gam[c] + bet[c];
        g_xn[(long long)row * Cc + c] = xn;
        out[(long long)row * Cc + c] = xn;
    }
}

__global__ void k_zero() { if (threadIdx.x < Ee) g_cursor[threadIdx.x] = 0; }

__global__ void k_gate(const float* __restrict__ gw) {
    int n = blockIdx.x;
    int wid = threadIdx.x >> 5, lane = threadIdx.x & 31;
    __shared__ float lg[Ee];
    const float* t = g_xn + (long long)n * Cc;
    const float* w = gw + wid * Cc;
    float s = 0.f;
    for (int c = lane; c < Cc; c += 32) s += t[c] * w[c];
    #pragma unroll
    for (int o = 16; o; o >>= 1) s += __shfl_xor_sync(0xffffffffu, s, o);
    if (lane == 0) lg[wid] = s;
    __syncthreads();
    if (threadIdx.x == 0) {
        float mx = lg[0];
        #pragma unroll
        for (int e = 1; e < Ee; e++) mx = fmaxf(mx, lg[e]);
        float p[Ee];
        #pragma unroll
        for (int e = 0; e < Ee; e++) p[e] = __expf(lg[e] - mx);
        int i1 = 0;
        #pragma unroll
        for (int e = 1; e < Ee; e++) if (p[e] > p[i1]) i1 = e;
        int i2 = (i1 == 0) ? 1 : 0;
        #pragma unroll
        for (int e = 0; e < Ee; e++) if (e != i1 && p[e] > p[i2]) i2 = e;
        float tot = p[i1] + p[i2];
        float w1 = p[i1] / tot, w2 = p[i2] / tot;
        int p1 = atomicAdd(&g_cursor[i1], 1);
        g_tok[i1 * NN + p1] = n; g_wgt[i1 * NN + p1] = w1;
        int p2 = atomicAdd(&g_cursor[i2], 1);
        g_tok[i2 * NN + p2] = n; g_wgt[i2 * NN + p2] = w2;
    }
}

// ========== gathered expert FC1, wmma tf32 + cp.async, a = h^2 * sigmoid(h) ==========
__global__ __launch_bounds__(256) void k_fc1(const float* __restrict__ fc1w,
                                             const float* __restrict__ fc1b) {
    int e = blockIdx.z;
    int cnt = g_cursor[e];
    int m0 = blockIdx.x * 128;
    if (m0 >= cnt) return;
    int n0 = blockIdx.y * 128;
    const float* Bw = fc1w + (long long)e * DFF * Cc;
    __shared__ float As[2][128][20];
    __shared__ float Bs[2][128][20];
    __shared__ int toks[128];
    const int tid = threadIdx.x, wid = tid >> 5, lane = tid & 31;
    const int mw = (wid >> 1) * 32, nw = (wid & 1) * 64;
    const int lr = tid >> 2, lc4 = (tid & 3) * 4;
    if (tid < 128) {
        int m = m0 + tid;
        toks[tid] = (m < cnt) ? g_tok[e * NN + m] : -1;
    }
    __syncthreads();
    FragC acc[2][4];
    #pragma unroll
    for (int i = 0; i < 2; i++)
        #pragma unroll
        for (int j = 0; j < 4; j++) wmma::fill_fragment(acc[i][j], 0.f);

    const int nIter = Cc / 16;   // 64
    #pragma unroll
    for (int p = 0; p < 2; p++) {
        int k0 = p * 16;
        #pragma unroll
        for (int rep = 0; rep < 2; rep++) {
            int r = lr + rep * 64;
            int tk = toks[r];
            cp16p(&As[p][r][lc4], &g_xn[(long long)(tk < 0 ? 0 : tk) * Cc + k0 + lc4], tk >= 0);
            cp16(&Bs[p][r][lc4], &Bw[(long long)(n0 + r) * Cc + k0 + lc4]);
        }
        CPCOMMIT;
    }
    for (int i = 0; i < nIter; i++) {
        if (i + 1 < nIter) { CPWAIT1; } else { CPWAIT0; }
        __syncthreads();
        int cur = i & 1;
        #pragma unroll
        for (int s = 0; s < 2; s++) {
            FragA af[2];
            FragBc bf[4];
            #pragma unroll
            for (int ii = 0; ii < 2; ii++)
                wmma::load_matrix_sync(af[ii], &As[cur][mw + ii * 16][s * 8], 20);
            #pragma unroll
            for (int j = 0; j < 4; j++)
                wmma::load_matrix_sync(bf[j], &Bs[cur][nw + j * 16][s * 8], 20);
            #pragma unroll
            for (int ii = 0; ii < 2; ii++)
                #pragma unroll
                for (int j = 0; j < 4; j++)
                    wmma::mma_sync(acc[ii][j], af[ii], bf[j], acc[ii][j]);
        }
        __syncthreads();
        if (i + 2 < nIter) {
            int k0 = (i + 2) * 16;
            #pragma unroll
            for (int rep = 0; rep < 2; rep++) {
                int r = lr + rep * 64;
                int tk = toks[r];
                cp16p(&As[cur][r][lc4], &g_xn[(long long)(tk < 0 ? 0 : tk) * Cc + k0 + lc4], tk >= 0);
                cp16(&Bs[cur][r][lc4], &Bw[(long long)(n0 + r) * Cc + k0 + lc4]);
            }
            CPCOMMIT;
        }
    }
    const float* bp = fc1b + e * DFF;
    float* stage = &As[0][0][0] + wid * 320;
    const int er = lane >> 1, ec0 = (lane & 1) * 8;
    #pragma unroll
    for (int i = 0; i < 2; i++) {
        #pragma unroll
        for (int j = 0; j < 4; j++) {
            wmma::store_matrix_sync(stage, acc[i][j], 20, wmma::mem_row_major);
            __syncwarp();
            int m = m0 + mw + i * 16 + er;
            if (m < cnt) {
                int n = n0 + nw + j * 16 + ec0;
                float vals[8];
                #pragma unroll
                for (int q = 0; q < 8; q++) {
                    float h = stage[er * 20 + ec0 + q] + bp[n + q];
                    vals[q] = h * h / (1.f + __expf(-h));   // h * silu(h)
                }
                float* op = &g_act[((long long)e * NN + m) * DFF + n];
                *reinterpret_cast<float4*>(op) = make_float4(vals[0], vals[1], vals[2], vals[3]);
                *reinterpret_cast<float4*>(op + 4) = make_float4(vals[4], vals[5], vals[6], vals[7]);
            }
            __syncwarp();
        }
    }
}

// ========== gathered expert FC2 + weighted scatter-add, wmma tf32 + cp.async ==========
__global__ __launch_bounds__(256) void k_fc2(const float* __restrict__ fc2w,
                                             const float* __restrict__ fc2b,
                                             float* __restrict__ out) {
    int e = blockIdx.z;
    int cnt = g_cursor[e];
    int m0 = blockIdx.x * 128;
    if (m0 >= cnt) return;
    int n0 = blockIdx.y * 128;
    const float* Aa = g_act + (long long)e * NN * DFF;
    const float* Bw = fc2w + (long long)e * Cc * DFF;
    __shared__ float As[2][128][20];
    __shared__ float Bs[2][128][20];
    const int tid = threadIdx.x, wid = tid >> 5, lane = tid & 31;
    const int mw = (wid >> 1) * 32, nw = (wid & 1) * 64;
    const int lr = tid >> 2, lc4 = (tid & 3) * 4;
    FragC acc[2][4];
    #pragma unroll
    for (int i = 0; i < 2; i++)
        #pragma unroll
        for (int j = 0; j < 4; j++) wmma::fill_fragment(acc[i][j], 0.f);

    const int nIter = DFF / 16;   // 64
    #pragma unroll
    for (int p = 0; p < 2; p++) {
        int k0 = p * 16;
        #pragma unroll
        for (int rep = 0; rep < 2; rep++) {
            int r = lr + rep * 64;
            cp16p(&As[p][r][lc4], &Aa[(long long)(m0 + r) * DFF + k0 + lc4], m0 + r < cnt);
            cp16(&Bs[p][r][lc4], &Bw[(long long)(n0 + r) * DFF + k0 + lc4]);
        }
        CPCOMMIT;
    }
    for (int i = 0; i < nIter; i++) {
        if (i + 1 < nIter) { CPWAIT1; } else { CPWAIT0; }
        __syncthreads();
        int cur = i & 1;
        #pragma unroll
        for (int s = 0; s < 2; s++) {
            FragA af[2];
            FragBc bf[4];
            #pragma unroll
            for (int ii = 0; ii < 2; ii++)
                wmma::load_matrix_sync(af[ii], &As[cur][mw + ii * 16][s * 8], 20);
            #pragma unroll
            for (int j = 0; j < 4; j++)
                wmma::load_matrix_sync(bf[j], &Bs[cur][nw + j * 16][s * 8], 20);
            #pragma unroll
            for (int ii = 0; ii < 2; ii++)
                #pragma unroll
                for (int j = 0; j < 4; j++)
                    wmma::mma_sync(acc[ii][j], af[ii], bf[j], acc[ii][j]);
        }
        __syncthreads();
        if (i + 2 < nIter) {
            int k0 = (i + 2) * 16;
            #pragma unroll
            for (int rep = 0; rep < 2; rep++) {
                int r = lr + rep * 64;
                cp16p(&As[cur][r][lc4], &Aa[(long long)(m0 + r) * DFF + k0 + lc4], m0 + r < cnt);
                cp16(&Bs[cur][r][lc4], &Bw[(long long)(n0 + r) * DFF + k0 + lc4]);
            }
            CPCOMMIT;
        }
    }
    const float* bp = fc2b + e * Cc;
    float* stage = &As[0][0][0] + wid * 320;
    const int er = lane >> 1, ec0 = (lane & 1) * 8;
    #pragma unroll
    for (int i = 0; i < 2; i++) {
        #pragma unroll
        for (int j = 0; j < 4; j++) {
            wmma::store_matrix_sync(stage, acc[i][j], 20, wmma::mem_row_major);
            __syncwarp();
            int m = m0 + mw + i * 16 + er;
            if (m < cnt) {
                int tk = g_tok[e * NN + m];
                float w = g_wgt[e * NN + m] * 0.5f;   // * RATIO
                int n = n0 + nw + j * 16 + ec0;
                #pragma unroll
                for (int q = 0; q < 8; q++) {
                    atomicAdd(&out[(long long)tk * Cc + n + q],
                              (stage[er * 20 + ec0 + q] + bp[n + q]) * w);
                }
            }
            __syncwarp();
        }
    }
}

// ---------------- launch ----------------
extern "C" void kernel_launch(void* const* d_in, const int* in_sizes, int n_in,
                              void* d_out, int out_size) {
    (void)in_sizes; (void)n_in; (void)out_size;
    const float* x       = (const float*)d_in[0];
    const float* qkv_w   = (const float*)d_in[1];
    const float* qkv_b   = (const float*)d_in[2];
    const float* aware_w = (const float*)d_in[3];
    const float* aware_b = (const float*)d_in[4];
    const float* dyn     = (const float*)d_in[5];
    const float* mw      = (const float*)d_in[6];
    const float* mb      = (const float*)d_in[7];
    const float* lng     = (const float*)d_in[8];
    const float* lnb     = (const float*)d_in[9];
    const float* gw      = (const float*)d_in[10];
    const float* f1w     = (const float*)d_in[11];
    const float* f1b     = (const float*)d_in[12];
    const float* f2w     = (const float*)d_in[13];
    const float* f2b     = (const float*)d_in[14];
    float* out = (float*)d_out;

    float *catp, *qkvp, *scoresp, *attnp, *yp, *scalep;
    cudaGetSymbolAddress((void**)&catp,    g_cat);
    cudaGetSymbolAddress((void**)&qkvp,    g_qkv);
    cudaGetSymbolAddress((void**)&scoresp, g_scores);
    cudaGetSymbolAddress((void**)&attnp,   g_attn);
    cudaGetSymbolAddress((void**)&yp,      g_y);
    cudaGetSymbolAddress((void**)&scalep,  g_scale);

    for (int i = 0; i < Pp; i++) {
        const float* xin = (i == 0) ? x : (catp + (i - 1) * Cc);
        int ldx = (i == 0) ? Cc : C3;

        k_colmean<<<dim3(Cc / 256, Bb), 256>>>(xin, ldx);
        k_aware<<<Bb * Hh, 256>>>(aware_w + (long long)i * Hh * Cc,
                                  aware_b + i * Hh, dyn + i);
        // qkv: (2048 x 1024) @ (3072 x 1024)^T + b -> g_qkv
        k_gemm_abT<<<dim3(NN / 128, C3 / 128, 1), 256>>>(
            xin, ldx, 0, 0,
            qkv_w + (long long)i * C3 * Cc, Cc, 0, 0,
            qkv_b + (long long)i * C3,
            qkvp, C3, 0, 0,
            Cc, 1, nullptr, nullptr, 0, 0);
        // scores: per (b,h): Q(1024x64) @ K^T, scaled by g_scale[z]
        k_gemm_abT<<<dim3(Tt / 128, Tt / 128, Bb * Hh), 256>>>(
            qkvp,       C3, (long long)Tt * C3, Dd,
            qkvp + Cc,  C3, (long long)Tt * C3, Dd,
            nullptr,
            scoresp, Tt, (long long)Hh * Tt * Tt, (long long)Tt * Tt,
            Dd, Hh, scalep, nullptr, 0, 0);
        // softmax + prior recurrence (writes g_attn)
        k_softmax_prior<<<Bb * Hh * Tt, 256>>>(i);
        // AV: attn(1024x1024) @ V(1024x64), silu, -> g_cat[:, i*C ...]
        k_gemm_ab_silu<<<dim3(Tt / 128, 1, Bb * Hh), 256>>>(
            attnp,          Tt, (long long)Hh * Tt * Tt, (long long)Tt * Tt,
            qkvp + 2 * Cc,  C3, (long long)Tt * C3, Dd,
            catp + i * Cc,  C3, (long long)Tt * C3, Dd,
            Tt, Hh);
    }

    // merger: (2048 x 3072) @ (1024 x 3072)^T + b + residual -> g_y
    k_gemm_abT<<<dim3(NN / 128, Cc / 128, 1), 256>>>(
        catp, C3, 0, 0,
        mw,   C3, 0, 0,
        mb,
        yp, Cc, 0, 0,
        C3, 1, nullptr, x, Cc, 0);

    k_layernorm<<<NN, 256>>>(lng, lnb, out);   // writes g_xn AND d_out=xn
    k_zero<<<1, 32>>>();
    k_gate<<<NN, 256>>>(gw);
    k_fc1<<<dim3(NN / 128, DFF / 128, Ee), 256>>>(f1w, f1b);
    k_fc2<<<dim3(NN / 128, Cc / 128, Ee), 256>>>(f2w, f2b, out);
}